// round 2
// baseline (speedup 1.0000x reference)
#include <cuda_runtime.h>
#include <math.h>

#define BB 8
#define NP 2048
#define EP 32768
#define NT (BB*NP)      // 16384 total nodes
#define ET (BB*EP)      // 262144 total edges
#define HH 128
#define NL 3
#define ES 50

// ---- scratch (no allocations allowed; __device__ globals) ----
__device__ float g_state[NT*HH];   // node states
__device__ float g_S[NT*HH];       // state @ Wn1_top  (sender half)
__device__ float g_R[NT*HH];       // state @ Wn1_bot  (receiver half)
__device__ float g_msum[NT*HH];    // per-node message accumulator
__device__ int   g_off[BB];        // exclusive cumsum of num_nodes

__device__ __forceinline__ float sspf(float x){
    // softplus(x) - log(2), numerically stable
    return fmaxf(x, 0.0f) + log1pf(__expf(-fabsf(x))) - 0.69314718055994530942f;
}

// ---------------------------------------------------------------------------
// init: node embedding gather + graph offsets
// ---------------------------------------------------------------------------
__global__ void k_init(const int* __restrict__ nodes, const float* __restrict__ emb,
                       const int* __restrict__ num_nodes){
    int i = blockIdx.x*blockDim.x + threadIdx.x;
    if (i == 0){
        int acc = 0;
        for (int b = 0; b < BB; b++){ g_off[b] = acc; acc += num_nodes[b]; }
    }
    if (i < NT*HH){
        int node = i >> 7, c = i & 127;
        g_state[i] = emb[nodes[node]*HH + c];
    }
}

__global__ void k_zero(){
    int i = blockIdx.x*blockDim.x + threadIdx.x;
    if (i < NT*HH) g_msum[i] = 0.0f;
}

// ---------------------------------------------------------------------------
// node pre-GEMM: S = state @ Wn1[:128], R = state @ Wn1[128:]
// 16 rows/block, 256 threads (threads <128 -> S cols, >=128 -> R cols)
// ---------------------------------------------------------------------------
__global__ void k_pre(const float* __restrict__ Wn1){
    __shared__ __align__(16) float As[16][HH];
    int t = threadIdx.x;
    int row0 = blockIdx.x*16;
    for (int i = t; i < 16*HH; i += 256)
        As[i>>7][i&127] = g_state[(row0 + (i>>7))*HH + (i&127)];
    __syncthreads();

    int half = t >> 7;
    int col  = t & 127;
    const float* W = Wn1 + half*HH*HH + col;
    float acc[16];
#pragma unroll
    for (int m = 0; m < 16; m++) acc[m] = 0.0f;
    for (int k = 0; k < HH; k += 4){
        float w0 = W[(k+0)*HH], w1 = W[(k+1)*HH], w2 = W[(k+2)*HH], w3 = W[(k+3)*HH];
#pragma unroll
        for (int m = 0; m < 16; m++){
            float4 a = *(const float4*)&As[m][k];
            acc[m] += a.x*w0 + a.y*w1 + a.z*w2 + a.w*w3;
        }
    }
    float* dst = half ? g_R : g_S;
#pragma unroll
    for (int m = 0; m < 16; m++) dst[(row0+m)*HH + col] = acc[m];
}

// ---------------------------------------------------------------------------
// edge kernel: per 16-edge tile
//   A1 = ssp(S[snd] + R[rcv] + bn1)           (hidden of node-pair MLP)
//   A2 = ssp(gauss(d) @ We1 + be1)            (hidden of edge-filter MLP)
//   msg = (A1@Wn2 + bn2) * ((A2@We2 + be2) * cut(d))
//   atomicAdd into g_msum[rcv]
// ---------------------------------------------------------------------------
__global__ void __launch_bounds__(128) k_edge(
    const int* __restrict__ atom_edges, const float* __restrict__ feats,
    const float* __restrict__ bn1, const float* __restrict__ Wn2, const float* __restrict__ bn2,
    const float* __restrict__ We1, const float* __restrict__ be1,
    const float* __restrict__ We2, const float* __restrict__ be2)
{
    __shared__ __align__(16) float As1[16][HH];
    __shared__ __align__(16) float As2[16][HH];
    __shared__ float es[16][ES];
    __shared__ float sd[16];
    __shared__ int   ssnd[16], srcv[16];

    int t  = threadIdx.x;
    int e0 = blockIdx.x*16;
    if (t < 16){
        int e   = e0 + t;
        int off = g_off[e / EP];
        ssnd[t] = atom_edges[e*2+0] + off;
        srcv[t] = atom_edges[e*2+1] + off;
        sd[t]   = feats[e];
    }
    __syncthreads();

    // gaussian radial basis: exp(-(d-mu)^2 / (2*0.1^2))
    for (int i = t; i < 16*ES; i += 128){
        int m = i / ES, j = i % ES;
        float dd = sd[m] - 0.1f*(float)j;
        es[m][j] = __expf(-dd*dd*50.0f);
    }
    // A1 (one smem column per thread)
    {
        float b = bn1[t];
#pragma unroll
        for (int m = 0; m < 16; m++){
            float v = g_S[ssnd[m]*HH + t] + g_R[srcv[m]*HH + t] + b;
            As1[m][t] = sspf(v);
        }
    }
    __syncthreads();

    // A2 = ssp(es @ We1 + be1)
    {
        float acc[16];
#pragma unroll
        for (int m = 0; m < 16; m++) acc[m] = 0.0f;
        for (int j = 0; j < ES; j++){
            float w = We1[j*HH + t];
#pragma unroll
            for (int m = 0; m < 16; m++) acc[m] += es[m][j]*w;
        }
        float b = be1[t];
#pragma unroll
        for (int m = 0; m < 16; m++) As2[m][t] = sspf(acc[m] + b);
    }
    __syncthreads();

    // dual GEMM: message path and gate path in one K loop
    float mn[16], gt[16];
#pragma unroll
    for (int m = 0; m < 16; m++){ mn[m] = 0.0f; gt[m] = 0.0f; }
    for (int k = 0; k < HH; k += 4){
        float w10 = Wn2[(k+0)*HH+t], w11 = Wn2[(k+1)*HH+t];
        float w12 = Wn2[(k+2)*HH+t], w13 = Wn2[(k+3)*HH+t];
        float w20 = We2[(k+0)*HH+t], w21 = We2[(k+1)*HH+t];
        float w22 = We2[(k+2)*HH+t], w23 = We2[(k+3)*HH+t];
#pragma unroll
        for (int m = 0; m < 16; m++){
            float4 a1 = *(const float4*)&As1[m][k];
            float4 a2 = *(const float4*)&As2[m][k];
            mn[m] += a1.x*w10 + a1.y*w11 + a1.z*w12 + a1.w*w13;
            gt[m] += a2.x*w20 + a2.y*w21 + a2.z*w22 + a2.w*w23;
        }
    }
    float b2 = bn2[t], be2v = be2[t];
#pragma unroll
    for (int m = 0; m < 16; m++){
        float d   = sd[m];
        float cut = 1.0f/(1.0f + __expf(5.0f*(d - 3.5f)));   // 1 - sigmoid(5(d-3.5))
        float msg = (mn[m] + b2) * ((gt[m] + be2v) * cut);
        atomicAdd(&g_msum[srcv[m]*HH + t], msg);
    }
}

// ---------------------------------------------------------------------------
// node update: state += ssp(msum @ Ws1 + bs1) @ Ws2 + bs2 ; write out slab
// ---------------------------------------------------------------------------
__global__ void k_upd(const float* __restrict__ Ws1, const float* __restrict__ bs1,
                      const float* __restrict__ Ws2, const float* __restrict__ bs2,
                      float* __restrict__ out)
{
    __shared__ __align__(16) float As[16][HH];
    __shared__ __align__(16) float Hs[16][HH];
    int t = threadIdx.x;
    int row0 = blockIdx.x*16;
    for (int i = t; i < 16*HH; i += 128)
        As[i>>7][i&127] = g_msum[(row0 + (i>>7))*HH + (i&127)];
    __syncthreads();

    float acc[16];
#pragma unroll
    for (int m = 0; m < 16; m++) acc[m] = 0.0f;
    for (int k = 0; k < HH; k += 4){
        float w0 = Ws1[(k+0)*HH+t], w1 = Ws1[(k+1)*HH+t];
        float w2 = Ws1[(k+2)*HH+t], w3 = Ws1[(k+3)*HH+t];
#pragma unroll
        for (int m = 0; m < 16; m++){
            float4 a = *(const float4*)&As[m][k];
            acc[m] += a.x*w0 + a.y*w1 + a.z*w2 + a.w*w3;
        }
    }
    float b1 = bs1[t];
#pragma unroll
    for (int m = 0; m < 16; m++) Hs[m][t] = sspf(acc[m] + b1);
    __syncthreads();

#pragma unroll
    for (int m = 0; m < 16; m++) acc[m] = 0.0f;
    for (int k = 0; k < HH; k += 4){
        float w0 = Ws2[(k+0)*HH+t], w1 = Ws2[(k+1)*HH+t];
        float w2 = Ws2[(k+2)*HH+t], w3 = Ws2[(k+3)*HH+t];
#pragma unroll
        for (int m = 0; m < 16; m++){
            float4 a = *(const float4*)&Hs[m][k];
            acc[m] += a.x*w0 + a.y*w1 + a.z*w2 + a.w*w3;
        }
    }
    float b2 = bs2[t];
#pragma unroll
    for (int m = 0; m < 16; m++){
        int idx = (row0+m)*HH + t;
        float v = g_state[idx] + acc[m] + b2;
        g_state[idx] = v;
        out[idx] = v;
    }
}

// ---------------------------------------------------------------------------
extern "C" void kernel_launch(void* const* d_in, const int* in_sizes, int n_in,
                              void* d_out, int out_size)
{
    const int*   nodes      = (const int*)  d_in[0];
    const int*   atom_edges = (const int*)  d_in[1];
    const float* feats      = (const float*)d_in[2];
    const int*   num_nodes  = (const int*)  d_in[3];
    // d_in[4] = num_atom_edges (all == EP, unused)
    const float* emb = (const float*)d_in[5];
    const float* Wn1 = (const float*)d_in[6];
    const float* bn1 = (const float*)d_in[7];
    const float* Wn2 = (const float*)d_in[8];
    const float* bn2 = (const float*)d_in[9];
    const float* We1 = (const float*)d_in[10];
    const float* be1 = (const float*)d_in[11];
    const float* We2 = (const float*)d_in[12];
    const float* be2 = (const float*)d_in[13];
    const float* Ws1 = (const float*)d_in[14];
    const float* bs1 = (const float*)d_in[15];
    const float* Ws2 = (const float*)d_in[16];
    const float* bs2 = (const float*)d_in[17];
    float* out = (float*)d_out;

    k_init<<<(NT*HH + 255)/256, 256>>>(nodes, emb, num_nodes);
    for (int l = 0; l < NL; l++){
        k_zero<<<(NT*HH + 255)/256, 256>>>();
        k_pre<<<NT/16, 256>>>(Wn1 + l*2*HH*HH);
        k_edge<<<ET/16, 128>>>(atom_edges, feats,
            bn1 + l*HH, Wn2 + l*HH*HH, bn2 + l*HH,
            We1 + l*ES*HH, be1 + l*HH, We2 + l*HH*HH, be2 + l*HH);
        k_upd<<<NT/16, 128>>>(Ws1 + l*HH*HH, bs1 + l*HH,
                              Ws2 + l*HH*HH, bs2 + l*HH,
                              out + (size_t)l*NT*HH);
    }
}